// round 6
// baseline (speedup 1.0000x reference)
#include <cuda_runtime.h>
#include <cuda_bf16.h>
#include <cstdint>

#define N_NODES 100000
#define N_EDGES 1250000
#define D       64
#define NBLK    391           // ceil(N_NODES/256)

// Scratch (no allocs allowed). CUDA zero-initializes device globals.
// Invariant: every kernel_launch invocation leaves g_deg and g_agg zeroed
// (k_norm consumes+clears deg; k_out consumes+clears agg), so graph replays
// are deterministic without dedicated zeroing kernels.
__device__ float g_agg[(size_t)N_NODES * D];
__device__ int   g_deg[N_NODES];
__device__ float g_norm[N_NODES];

// ---------------------------------------------------------------------------
// K1: degree count, 4 edges/thread, no-return reductions (REDG)
__global__ void k_deg(const int* __restrict__ dst) {
    int t = blockIdx.x * 256 + threadIdx.x;
    if (t >= N_EDGES / 4) return;
    int4 d4 = *reinterpret_cast<const int4*>(dst + t * 4);
    asm volatile("red.global.add.u32 [%0], 1;" :: "l"(&g_deg[d4.x]) : "memory");
    asm volatile("red.global.add.u32 [%0], 1;" :: "l"(&g_deg[d4.y]) : "memory");
    asm volatile("red.global.add.u32 [%0], 1;" :: "l"(&g_deg[d4.z]) : "memory");
    asm volatile("red.global.add.u32 [%0], 1;" :: "l"(&g_deg[d4.w]) : "memory");
}

// K2: norm = clip(deg,1)^-0.5 ; consume-and-clear deg for next replay
__global__ void k_norm() {
    int i = blockIdx.x * 256 + threadIdx.x;
    if (i < N_NODES) {
        int d = g_deg[i];
        g_norm[i] = rsqrtf(fmaxf((float)d, 1.0f));
        g_deg[i] = 0;
    }
}

// K3: edge scatter: agg[dst] += feat[src] * norm[src]
// 16 lanes per edge-group; 4 edges per thread (MLP: 4 norm + 4 float4 gathers in flight)
__global__ void k_scatter(const float* __restrict__ feat,
                          const int* __restrict__ src,
                          const int* __restrict__ dst) {
    int t = blockIdx.x * 256 + threadIdx.x;
    int grp = t >> 4;
    int sub = t & 15;
    if (grp >= N_EDGES / 4) return;
    int e0 = grp * 4;
    int4 s4 = *reinterpret_cast<const int4*>(src + e0);
    int4 d4 = *reinterpret_cast<const int4*>(dst + e0);
    int s[4] = {s4.x, s4.y, s4.z, s4.w};
    int d[4] = {d4.x, d4.y, d4.z, d4.w};

    float  nm[4];
    float4 v[4];
#pragma unroll
    for (int i = 0; i < 4; i++) nm[i] = __ldg(&g_norm[s[i]]);
#pragma unroll
    for (int i = 0; i < 4; i++)
        v[i] = *reinterpret_cast<const float4*>(feat + (size_t)s[i] * D + sub * 4);
#pragma unroll
    for (int i = 0; i < 4; i++) {
        float4 w = v[i];
        w.x *= nm[i]; w.y *= nm[i]; w.z *= nm[i]; w.w *= nm[i];
        float* p = g_agg + (size_t)d[i] * D + sub * 4;
        asm volatile("red.global.add.v4.f32 [%0], {%1, %2, %3, %4};"
                     :: "l"(p), "f"(w.x), "f"(w.y), "f"(w.z), "f"(w.w)
                     : "memory");
    }
}

// ---------------------------------------------------------------------------
// K4: out = (agg * norm) @ W^T + bias, packed f32x2 FMA.
// Also consume-and-clear agg (stores zeros while staging) for next replay.
#define WT_PAD 68
#define A_PAD  65
#define SMEM_OUT_BYTES ((64 * WT_PAD + 256 * A_PAD) * 4)   // 83,968 B

__global__ void __launch_bounds__(256, 2)
k_out(const float* __restrict__ W,
      const float* __restrict__ bias,
      float* __restrict__ out) {
    extern __shared__ float sm[];
    float* w_sm = sm;                 // [64][WT_PAD]  w_sm[k][j] = W[j][k]
    float* a_sm = sm + 64 * WT_PAD;   // [256][A_PAD]
    int tid = threadIdx.x;

    for (int i = tid; i < 64 * 64; i += 256) {
        int j = i >> 6, k = i & 63;
        w_sm[k * WT_PAD + j] = W[i];
    }
    int nbase = blockIdx.x * 256;
#pragma unroll
    for (int it = 0; it < 16; it++) {
        int li = tid + it * 256;
        int nl = li >> 4, k4 = (li & 15) << 2;
        int n = nbase + nl;
        if (n < N_NODES) {
            float4* gp = reinterpret_cast<float4*>(g_agg + (size_t)n * D + k4);
            float4 v = *gp;
            float nm = __ldg(&g_norm[n]);
            *gp = make_float4(0.f, 0.f, 0.f, 0.f);     // clear for next replay
            float* ap = a_sm + nl * A_PAD + k4;
            ap[0] = v.x * nm; ap[1] = v.y * nm; ap[2] = v.z * nm; ap[3] = v.w * nm;
        } else {
            float* ap = a_sm + nl * A_PAD + k4;
            ap[0] = 0.f; ap[1] = 0.f; ap[2] = 0.f; ap[3] = 0.f;
        }
    }
    __syncthreads();

    unsigned long long acc[32];
#pragma unroll
    for (int i = 0; i < 32; i++)
        acc[i] = __ldg(reinterpret_cast<const unsigned long long*>(bias) + i);

    const float* arow = a_sm + tid * A_PAD;
#pragma unroll 4
    for (int k = 0; k < 64; k++) {
        float ak = arow[k];
        unsigned long long ak2;
        asm("mov.b64 %0, {%1, %1};" : "=l"(ak2) : "r"(__float_as_uint(ak)));
        const unsigned long long* wrow =
            reinterpret_cast<const unsigned long long*>(w_sm + k * WT_PAD);
#pragma unroll
        for (int i = 0; i < 32; i++)
            asm("fma.rn.f32x2 %0, %1, %2, %0;" : "+l"(acc[i]) : "l"(ak2), "l"(wrow[i]));
    }

    int n = nbase + tid;
    if (n < N_NODES) {
        ulonglong2* o = reinterpret_cast<ulonglong2*>(out + (size_t)n * D);
#pragma unroll
        for (int i = 0; i < 16; i++) o[i] = make_ulonglong2(acc[2 * i], acc[2 * i + 1]);
    }
}

// ---------------------------------------------------------------------------
extern "C" void kernel_launch(void* const* d_in, const int* in_sizes, int n_in,
                              void* d_out, int out_size) {
    const float* feat = (const float*)d_in[0];
    const int*   src  = (const int*)d_in[1];
    const int*   dst  = (const int*)d_in[2];
    const float* W    = (const float*)d_in[3];
    const float* bias = (const float*)d_in[4];
    float* out = (float*)d_out;

    static bool attr_set = false;
    if (!attr_set) {
        cudaFuncSetAttribute(k_out, cudaFuncAttributeMaxDynamicSharedMemorySize,
                             SMEM_OUT_BYTES);
        attr_set = true;
    }

    k_deg<<<(N_EDGES / 4 + 255) / 256, 256>>>(dst);
    k_norm<<<NBLK, 256>>>();
    k_scatter<<<(N_EDGES / 4 * 16 + 255) / 256, 256>>>(feat, src, dst);
    k_out<<<NBLK, 256, SMEM_OUT_BYTES>>>(W, bias, out);
}